// round 8
// baseline (speedup 1.0000x reference)
#include <cuda_runtime.h>

// SSKernelNPLR: H=256, N=64, c=1, rank=1, L=2048.
// R6 (resubmit after infra failure):
//  K1: Cauchy+Woodbury. 1024 blocks (256 heads x 4 chunks) x 64 threads,
//      4 freq nodes/thread (amortize broadcast LDS 4x, 4 indep chains).
//  K2: c2r half-length trick: pack Hermitian 2048-spectrum into 1024-pt
//      complex inverse Stockham FFT; interleaved float2 output store.

#define NSTATE 64
#define LFULL  2048
#define MHALF  1024

typedef unsigned long long u64;

__device__ float2 g_spec[256 * 1025];   // 2.05 MB scratch spectrum

__device__ __forceinline__ u64 pk2(float lo, float hi) {
    u64 r; asm("mov.b64 %0,{%1,%2};" : "=l"(r) : "f"(lo), "f"(hi)); return r;
}
__device__ __forceinline__ void up2(u64 v, float& lo, float& hi) {
    asm("mov.b64 {%0,%1},%2;" : "=f"(lo), "=f"(hi) : "l"(v));
}
__device__ __forceinline__ u64 ffma2(u64 a, u64 b, u64 c) {
    u64 r; asm("fma.rn.f32x2 %0,%1,%2,%3;" : "=l"(r) : "l"(a), "l"(b), "l"(c)); return r;
}
__device__ __forceinline__ float frcp(float x) {
    float r; asm("rcp.approx.f32 %0,%1;" : "=f"(r) : "f"(x)); return r;
}
__device__ __forceinline__ float2 cmul(float2 a, float2 b) {
    return make_float2(a.x * b.x - a.y * b.y, a.x * b.y + a.y * b.x);
}

// ---------------- K1: Cauchy + Woodbury ----------------
__global__ __launch_bounds__(64)
void cauchy_kernel(const float* __restrict__ Cin,
                   const float* __restrict__ Bin,
                   const float* __restrict__ Pin,
                   const float* __restrict__ Win,
                   const float* __restrict__ log_dt)
{
    __shared__ float2 swd[NSTATE];     // (-w*dt)
    __shared__ u64 svA[4][NSTATE];     // pk(vx, -vx)   (v00,v01,v10,v11)
    __shared__ u64 svB[3][NSTATE];     // pk(vy,  vy)   (v11 imag == 0)

    const int bid   = blockIdx.x;
    const int h     = bid >> 2;
    const int chunk = bid & 3;
    const int tid   = threadIdx.x;     // 0..63
    const float dt  = expf(log_dt[h]);

    {
        const int base = (h * NSTATE + tid) * 2;
        float2 b = make_float2(Bin[base], Bin[base + 1]);
        float2 c = make_float2(Cin[base], Cin[base + 1]);
        float2 p = make_float2(Pin[base], Pin[base + 1]);
        float2 q = make_float2(p.x, -p.y);          // Q = conj(P)
        swd[tid] = make_float2(-Win[base] * dt, -Win[base + 1] * dt);
        float2 v;
        v = cmul(b, c); svA[0][tid] = pk2(v.x, -v.x); svB[0][tid] = pk2(v.y, v.y);
        v = cmul(b, q); svA[1][tid] = pk2(v.x, -v.x); svB[1][tid] = pk2(v.y, v.y);
        v = cmul(p, c); svA[2][tid] = pk2(v.x, -v.x); svB[2][tid] = pk2(v.y, v.y);
        float v11 = p.x * p.x + p.y * p.y;          // P*conj(P) is real
        svA[3][tid] = pk2(v11, -v11);
    }
    __syncthreads();

    // four frequency nodes per thread: f = chunk*256 + k*64 + tid
    float zx[4], zy[4];
    float2 facv[4];
    #pragma unroll
    for (int k = 0; k < 4; k++) {
        const int f = chunk * 256 + k * 64 + tid;   // 0..1023
        float s, c;
        sincospif((float)f * (1.0f / MHALF), &s, &c);
        float2 om = make_float2(c, -s);             // exp(-2*pi*i*f/L)
        float ex = 1.0f + om.x, ey = om.y;          // 1 + omega
        float inv_e2 = frcp(ex * ex + ey * ey);
        float ax = 1.0f - om.x, ay = -om.y;         // 1 - omega
        zx[k] = 2.0f * (ax * ex + ay * ey) * inv_e2;
        zy[k] = 2.0f * (ay * ex - ax * ey) * inv_e2;
        facv[k] = make_float2(2.0f * ex * inv_e2, -2.0f * ey * inv_e2);
    }

    u64 acc[4][4];
    #pragma unroll
    for (int k = 0; k < 4; k++)
        #pragma unroll
        for (int a = 0; a < 4; a++) acc[k][a] = 0ull;

    #pragma unroll 2
    for (int n = 0; n < NSTATE; n++) {
        const float2 wd = swd[n];
        const u64 a0 = svA[0][n], a1 = svA[1][n], a2 = svA[2][n], a3 = svA[3][n];
        const u64 b0 = svB[0][n], b1 = svB[1][n], b2 = svB[2][n];
        #pragma unroll
        for (int k = 0; k < 4; k++) {
            float dx = zx[k] + wd.x;                // z - w*dt (wd pre-negated)
            float dy = zy[k] + wd.y;
            float r  = frcp(dx * dx + dy * dy);
            float ur = dx * r, ui = dy * r;         // 1/d = (ur, -ui)
            u64 P1 = pk2(ur, ui);
            u64 P2 = pk2(ui, ur);
            acc[k][0] = ffma2(a0, P1, acc[k][0]); acc[k][0] = ffma2(b0, P2, acc[k][0]);
            acc[k][1] = ffma2(a1, P1, acc[k][1]); acc[k][1] = ffma2(b1, P2, acc[k][1]);
            acc[k][2] = ffma2(a2, P1, acc[k][2]); acc[k][2] = ffma2(b2, P2, acc[k][2]);
            acc[k][3] = ffma2(a3, P1, acc[k][3]);   // v11 real: no imag term
        }
    }

    #pragma unroll
    for (int k = 0; k < 4; k++) {
        const int f = chunk * 256 + k * 64 + tid;
        float2 r00, r01, r10, r11;
        up2(acc[k][0], r00.x, r00.y); up2(acc[k][1], r01.x, r01.y);
        up2(acc[k][2], r10.x, r10.y); up2(acc[k][3], r11.x, r11.y);
        r00.x *= dt; r00.y *= dt;  r01.x *= dt; r01.y *= dt;
        r10.x *= dt; r10.y *= dt;  r11.x *= dt; r11.y *= dt;
        // num = r00 - r01*r10/(1+r11)
        float2 t = cmul(r01, r10);
        float2 d = make_float2(1.0f + r11.x, r11.y);
        float iD = frcp(d.x * d.x + d.y * d.y);
        float2 t2 = make_float2((t.x * d.x + t.y * d.y) * iD,
                                (t.y * d.x - t.x * d.y) * iD);
        float2 kf = cmul(make_float2(r00.x - t2.x, r00.y - t2.y), facv[k]);
        g_spec[h * 1025 + f] = kf;
    }

    // f = 1024 (omega = -1 analytic limit): k_f = 0.5*dt*sum_n v00
    if (chunk == 0 && tid == 0) {
        float sx = 0.f, sy = 0.f;
        #pragma unroll 8
        for (int n = 0; n < NSTATE; n++) {
            float vx, vxn, vy, du;
            up2(svA[0][n], vx, vxn);
            up2(svB[0][n], vy, du);
            sx += vx; sy += vy;
        }
        g_spec[h * 1025 + 1024] = make_float2(0.5f * dt * sx, 0.5f * dt * sy);
    }
}

// ---------------- K2: c2r inverse FFT via 1024-pt complex iFFT ----------------
__global__ __launch_bounds__(256)
void ifft_kernel(float* __restrict__ out)
{
    __shared__ float2 X[MHALF];        // ping (8 KB)
    __shared__ float2 Y[MHALF];        // pong (8 KB)
    __shared__ float2 T[MHALF / 2];    // twiddles exp(+2*pi*i*j/1024) (4 KB)

    const int h   = blockIdx.x;
    const int tid = threadIdx.x;

    for (int j = tid; j < MHALF / 2; j += 256) {
        float s, c;
        sincospif((float)j * (1.0f / (MHALF / 2)), &s, &c);
        T[j] = make_float2(c, s);
    }

    // pack: Z[k] = E + i*W*O,  E = X[k]+conj(X[1024-k]), O = X[k]-conj(X[1024-k]),
    // W = exp(+i*pi*k/1024).  Bins 0 and 1024: use real parts only.
    const float2* spec = g_spec + h * 1025;
    for (int k = tid; k < MHALF; k += 256) {
        float2 Xa = spec[k];
        float2 Xm = spec[MHALF - k];
        if (k == 0) { Xa.y = 0.0f; Xm.y = 0.0f; }
        // Xb = conj(Xm)
        float Ex = Xa.x + Xm.x,  Ey = Xa.y - Xm.y;
        float Ox = Xa.x - Xm.x,  Oy = Xa.y + Xm.y;
        float s, c;
        sincospif((float)k * (1.0f / MHALF), &s, &c);
        // i*W*O = (-(c*Oy + s*Ox), c*Ox - s*Oy)
        X[k] = make_float2(Ex - (c * Oy + s * Ox), Ey + (c * Ox - s * Oy));
    }
    __syncthreads();

    // 1024-pt inverse complex FFT (Stockham, 10 stages, ends in X)
    float2* src = X;
    float2* dst = Y;
    for (int m = 1; m <= MHALF / 2; m <<= 1) {
        for (int b = tid; b < MHALF / 2; b += 256) {
            int jm = b & ~(m - 1);
            float2 c0 = src[b];
            float2 c1 = src[b + MHALF / 2];
            float2 w  = T[jm];
            dst[b + jm]     = make_float2(c0.x + c1.x, c0.y + c1.y);
            float2 df = make_float2(c0.x - c1.x, c0.y - c1.y);
            dst[b + jm + m] = cmul(w, df);
        }
        __syncthreads();
        float2* tmp = src; src = dst; dst = tmp;
    }

    // z[n] = out[2n] + i*out[2n+1]  -> coalesced float2 store
    const float scale = 1.0f / (float)LFULL;
    float2* o2 = (float2*)(out + (size_t)h * LFULL);
    for (int n = tid; n < MHALF; n += 256) {
        float2 z = src[n];
        o2[n] = make_float2(z.x * scale, z.y * scale);
    }
}

extern "C" void kernel_launch(void* const* d_in, const int* in_sizes, int n_in,
                              void* d_out, int out_size)
{
    (void)in_sizes; (void)n_in; (void)out_size;
    const float* C  = (const float*)d_in[0];
    const float* B  = (const float*)d_in[1];
    const float* P  = (const float*)d_in[2];
    const float* W  = (const float*)d_in[3];
    const float* ld = (const float*)d_in[4];
    float* out = (float*)d_out;
    cauchy_kernel<<<1024, 64>>>(C, B, P, W, ld);
    ifft_kernel<<<256, 256>>>(out);
}

// round 9
// speedup vs baseline: 1.7146x; 1.7146x over previous
#include <cuda_runtime.h>

// SSKernelNPLR: H=256, N=64, c=1, rank=1, L=2048.
// R8:
//  K1: revert to R5 shape (1024 blocks x 128 thr, 2 nodes/thread) + LDS.128
//      operand interleave (4x ulonglong2 per n instead of 8x LDS.64).
//  K2: radix-4 Stockham (5 stages), 2 heads per 512-thread block (grid=128,
//      one wave), c2r half-length packing.

#define NSTATE 64
#define LFULL  2048
#define MHALF  1024

typedef unsigned long long u64;

__device__ float2 g_spec[256 * 1025];   // 2.05 MB scratch spectrum

__device__ __forceinline__ u64 pk2(float lo, float hi) {
    u64 r; asm("mov.b64 %0,{%1,%2};" : "=l"(r) : "f"(lo), "f"(hi)); return r;
}
__device__ __forceinline__ void up2(u64 v, float& lo, float& hi) {
    asm("mov.b64 {%0,%1},%2;" : "=f"(lo), "=f"(hi) : "l"(v));
}
__device__ __forceinline__ u64 ffma2(u64 a, u64 b, u64 c) {
    u64 r; asm("fma.rn.f32x2 %0,%1,%2,%3;" : "=l"(r) : "l"(a), "l"(b), "l"(c)); return r;
}
__device__ __forceinline__ float frcp(float x) {
    float r; asm("rcp.approx.f32 %0,%1;" : "=f"(r) : "f"(x)); return r;
}
__device__ __forceinline__ float2 cmul(float2 a, float2 b) {
    return make_float2(a.x * b.x - a.y * b.y, a.x * b.y + a.y * b.x);
}

// ---------------- K1: Cauchy + Woodbury ----------------
__global__ __launch_bounds__(128)
void cauchy_kernel(const float* __restrict__ Cin,
                   const float* __restrict__ Bin,
                   const float* __restrict__ Pin,
                   const float* __restrict__ Win,
                   const float* __restrict__ log_dt)
{
    // interleaved operands: sv2[n] = { {a0,b0}, {a1,b1}, {a2,b2}, {a3,wd} }
    // aX = pk(vX.x, -vX.x), bX = pk(vX.y, vX.y), wd = pk(-w.x*dt, -w.y*dt)
    __shared__ ulonglong2 sv2[NSTATE][4];

    const int bid   = blockIdx.x;
    const int h     = bid >> 2;
    const int chunk = bid & 3;
    const int tid   = threadIdx.x;     // 0..127
    const float dt  = expf(log_dt[h]);

    if (tid < NSTATE) {
        const int base = (h * NSTATE + tid) * 2;
        float2 b = make_float2(Bin[base], Bin[base + 1]);
        float2 c = make_float2(Cin[base], Cin[base + 1]);
        float2 p = make_float2(Pin[base], Pin[base + 1]);
        float2 q = make_float2(p.x, -p.y);          // Q = conj(P)
        u64 wd = pk2(-Win[base] * dt, -Win[base + 1] * dt);
        float2 v;
        v = cmul(b, c);
        sv2[tid][0] = make_ulonglong2(pk2(v.x, -v.x), pk2(v.y, v.y));
        v = cmul(b, q);
        sv2[tid][1] = make_ulonglong2(pk2(v.x, -v.x), pk2(v.y, v.y));
        v = cmul(p, c);
        sv2[tid][2] = make_ulonglong2(pk2(v.x, -v.x), pk2(v.y, v.y));
        float v11 = p.x * p.x + p.y * p.y;          // P*conj(P) is real
        sv2[tid][3] = make_ulonglong2(pk2(v11, -v11), wd);
    }
    __syncthreads();

    // two frequency nodes per thread: f = chunk*256 + k*128 + tid
    float zx[2], zy[2];
    float2 facv[2];
    #pragma unroll
    for (int k = 0; k < 2; k++) {
        const int f = chunk * 256 + k * 128 + tid;  // 0..1023
        float s, c;
        sincospif((float)f * (1.0f / MHALF), &s, &c);
        float2 om = make_float2(c, -s);             // exp(-2*pi*i*f/L)
        float ex = 1.0f + om.x, ey = om.y;          // 1 + omega
        float inv_e2 = frcp(ex * ex + ey * ey);
        float ax = 1.0f - om.x, ay = -om.y;         // 1 - omega
        zx[k] = 2.0f * (ax * ex + ay * ey) * inv_e2;
        zy[k] = 2.0f * (ay * ex - ax * ey) * inv_e2;
        facv[k] = make_float2(2.0f * ex * inv_e2, -2.0f * ey * inv_e2);
    }

    u64 acc[2][4];
    #pragma unroll
    for (int k = 0; k < 2; k++)
        #pragma unroll
        for (int a = 0; a < 4; a++) acc[k][a] = 0ull;

    #pragma unroll 4
    for (int n = 0; n < NSTATE; n++) {
        const ulonglong2 p0 = sv2[n][0];
        const ulonglong2 p1 = sv2[n][1];
        const ulonglong2 p2 = sv2[n][2];
        const ulonglong2 p3 = sv2[n][3];
        float wdx, wdy; up2(p3.y, wdx, wdy);
        #pragma unroll
        for (int k = 0; k < 2; k++) {
            float dx = zx[k] + wdx;                 // z - w*dt (pre-negated)
            float dy = zy[k] + wdy;
            float r  = frcp(dx * dx + dy * dy);
            float ur = dx * r, ui = dy * r;         // 1/d = (ur, -ui)
            u64 P1 = pk2(ur, ui);
            u64 P2 = pk2(ui, ur);
            acc[k][0] = ffma2(p0.x, P1, acc[k][0]); acc[k][0] = ffma2(p0.y, P2, acc[k][0]);
            acc[k][1] = ffma2(p1.x, P1, acc[k][1]); acc[k][1] = ffma2(p1.y, P2, acc[k][1]);
            acc[k][2] = ffma2(p2.x, P1, acc[k][2]); acc[k][2] = ffma2(p2.y, P2, acc[k][2]);
            acc[k][3] = ffma2(p3.x, P1, acc[k][3]); // v11 real: no imag term
        }
    }

    #pragma unroll
    for (int k = 0; k < 2; k++) {
        const int f = chunk * 256 + k * 128 + tid;
        float2 r00, r01, r10, r11;
        up2(acc[k][0], r00.x, r00.y); up2(acc[k][1], r01.x, r01.y);
        up2(acc[k][2], r10.x, r10.y); up2(acc[k][3], r11.x, r11.y);
        r00.x *= dt; r00.y *= dt;  r01.x *= dt; r01.y *= dt;
        r10.x *= dt; r10.y *= dt;  r11.x *= dt; r11.y *= dt;
        // num = r00 - r01*r10/(1+r11)
        float2 t = cmul(r01, r10);
        float2 d = make_float2(1.0f + r11.x, r11.y);
        float iD = frcp(d.x * d.x + d.y * d.y);
        float2 t2 = make_float2((t.x * d.x + t.y * d.y) * iD,
                                (t.y * d.x - t.x * d.y) * iD);
        float2 kf = cmul(make_float2(r00.x - t2.x, r00.y - t2.y), facv[k]);
        g_spec[h * 1025 + f] = kf;
    }

    // f = 1024 (omega = -1 analytic limit): k_f = 0.5*dt*sum_n v00
    if (chunk == 0 && tid == 0) {
        float sx = 0.f, sy = 0.f;
        #pragma unroll 8
        for (int n = 0; n < NSTATE; n++) {
            float vx, vxn, vy, du;
            up2(sv2[n][0].x, vx, vxn);
            up2(sv2[n][0].y, vy, du);
            sx += vx; sy += vy;
        }
        g_spec[h * 1025 + 1024] = make_float2(0.5f * dt * sx, 0.5f * dt * sy);
    }
}

// ---------------- K2: c2r iFFT via radix-4 Stockham, 2 heads/block ----------------
__global__ __launch_bounds__(512)
void ifft_kernel(float* __restrict__ out)
{
    __shared__ float2 X[2][MHALF];     // ping (16 KB)
    __shared__ float2 Y[2][MHALF];     // pong (16 KB)
    __shared__ float2 T[768];          // exp(+2*pi*i*j/1024), j<768 (6 KB)

    const int t   = threadIdx.x;       // 0..511
    const int hs  = t >> 8;            // head slot 0/1
    const int l   = t & 255;           // local lane within head
    const int h   = blockIdx.x * 2 + hs;

    for (int j = t; j < 768; j += 512) {
        float s, c;
        sincospif((float)j * (1.0f / 512.0f), &s, &c);   // angle = 2*pi*j/1024
        T[j] = make_float2(c, s);
    }

    // pack: Z[k] = E + i*W*O,  E = S[k]+conj(S[1024-k]), O = S[k]-conj(S[1024-k]),
    // W = exp(+i*pi*k/1024).  k==0 uses real parts of bins 0 and 1024 only.
    const float2* spec = g_spec + h * 1025;
    #pragma unroll
    for (int j = 0; j < 4; j++) {
        int k = l + j * 256;
        float2 Xa = spec[k];
        float2 Xm = spec[MHALF - k];
        if (k == 0) { Xa.y = 0.0f; Xm.y = 0.0f; }
        float Ex = Xa.x + Xm.x,  Ey = Xa.y - Xm.y;
        float Ox = Xa.x - Xm.x,  Oy = Xa.y + Xm.y;
        float s, c;
        sincospif((float)k * (1.0f / MHALF), &s, &c);    // angle = pi*k/1024
        X[hs][k] = make_float2(Ex - (c * Oy + s * Ox), Ey + (c * Ox - s * Oy));
    }
    __syncthreads();

    // 1024-pt inverse complex FFT: radix-4 Stockham, stages m = 1,4,16,64,256.
    // butterfly (per t in [0,256), jm = t&~(m-1), r = t&(m-1)):
    //   u0..u3 = src[t + {0,256,512,768}]
    //   dst[4*jm + r + {0,m,2m,3m}] =
    //     { (u0+u2)+(u1+u3),
    //       T[jm]  * ((u0-u2) + i(u1-u3)),
    //       T[2jm] * ((u0+u2) - (u1+u3)),
    //       T[3jm] * ((u0-u2) - i(u1-u3)) }
    float2* src = X[hs];
    float2* dst = Y[hs];
    #pragma unroll
    for (int m = 1; m <= 256; m <<= 2) {
        int jm = l & ~(m - 1);
        int r  = l & (m - 1);
        float2 u0 = src[l];
        float2 u1 = src[l + 256];
        float2 u2 = src[l + 512];
        float2 u3 = src[l + 768];
        float2 e  = make_float2(u0.x + u2.x, u0.y + u2.y);
        float2 o  = make_float2(u0.x - u2.x, u0.y - u2.y);
        float2 ep = make_float2(u1.x + u3.x, u1.y + u3.y);
        float2 op = make_float2(u1.x - u3.x, u1.y - u3.y);
        float2 iop = make_float2(-op.y, op.x);            // i*(u1-u3)
        float2 w1 = T[jm];
        float2 w2 = T[2 * jm];
        float2 w3 = T[3 * jm];
        int base = 4 * jm + r;
        dst[base]         = make_float2(e.x + ep.x, e.y + ep.y);
        dst[base + m]     = cmul(w1, make_float2(o.x + iop.x, o.y + iop.y));
        dst[base + 2 * m] = cmul(w2, make_float2(e.x - ep.x, e.y - ep.y));
        dst[base + 3 * m] = cmul(w3, make_float2(o.x - iop.x, o.y - iop.y));
        __syncthreads();
        float2* tmp = src; src = dst; dst = tmp;
    }
    // 5 stages -> result ends in Y[hs] (== src after final swap)

    // z[n] = out[2n] + i*out[2n+1]  -> coalesced float2 store
    const float scale = 1.0f / (float)LFULL;
    float2* o2 = (float2*)(out + (size_t)h * LFULL);
    #pragma unroll
    for (int j = 0; j < 4; j++) {
        int n = l + j * 256;
        float2 z = src[n];
        o2[n] = make_float2(z.x * scale, z.y * scale);
    }
}

extern "C" void kernel_launch(void* const* d_in, const int* in_sizes, int n_in,
                              void* d_out, int out_size)
{
    (void)in_sizes; (void)n_in; (void)out_size;
    const float* C  = (const float*)d_in[0];
    const float* B  = (const float*)d_in[1];
    const float* P  = (const float*)d_in[2];
    const float* W  = (const float*)d_in[3];
    const float* ld = (const float*)d_in[4];
    float* out = (float*)d_out;
    cauchy_kernel<<<1024, 128>>>(C, B, P, W, ld);
    ifft_kernel<<<128, 512>>>(out);
}